// round 4
// baseline (speedup 1.0000x reference)
#include <cuda_runtime.h>
#include <cuda_bf16.h>

#define NB 256
#define NT 4096
#define ND 3
#define NU 8

static __device__ __forceinline__ float tanha(float x) {
    float y; asm("tanh.approx.f32 %0, %1;" : "=f"(y) : "f"(x)); return y;
}
static __device__ __forceinline__ float sigm(float x) {      // exact identity, approx only via TANH
    return fmaf(tanha(0.5f * x), 0.5f, 0.5f);
}
static __device__ __forceinline__ float frcpa(float x) {
    float y; asm("rcp.approx.f32 %0, %1;" : "=f"(y) : "f"(x)); return y;
}

// ---- C-part: advance signature to step T_+1, compute fg/xproj for step T_+1 ----
// (forget gate & x-proj depend only on inputs -> pipelined one step ahead, off critical chain)
#define STEP_C(T_, SLOT_)                                                          \
    do {                                                                           \
        float xn0 = xb0[SLOT_], xn1 = xb1[SLOT_], xn2 = xb2[SLOT_];                \
        {   int tp_ = (T_) + 9; if (tp_ > NT - 1) tp_ = NT - 1;                    \
            xb0[SLOT_] = xin[tp_ * 3 + 0];                                         \
            xb1[SLOT_] = xin[tp_ * 3 + 1];                                         \
            xb2[SLOT_] = xin[tp_ * 3 + 2]; }                                       \
        tf += 1.0f;                                                                \
        float d1 = xn0 - px0, d2 = xn1 - px1, d3 = xn2 - px2;                      \
        px0 = xn0; px1 = xn1; px2 = xn2;                                           \
        float mydx = (g == 0) ? DX0 : ((g == 1) ? d1 : ((g == 2) ? d2 : d3));      \
        float q = fmaf(0.5f, mydx, L1g);         /* Chen: (L1_prev + dx/2) (x) dx */\
        L2r0 = fmaf(q, DX0, L2r0); L2r1 = fmaf(q, d1, L2r1);                       \
        L2r2 = fmaf(q, d2,  L2r2); L2r3 = fmaf(q, d3, L2r3);                       \
        L1g += mydx;                                                               \
        float p = fmaf(L1g, fL1, fbase);         /* per-group partial of sig.F */  \
        p = fmaf(L2r0, fR0, p); p = fmaf(L2r1, fR1, p);                            \
        p = fmaf(L2r2, fR2, p); p = fmaf(L2r3, fR3, p);                            \
        p += __shfl_xor_sync(0xffffffffu, p, 8);                                   \
        p += __shfl_xor_sync(0xffffffffu, p, 16);                                  \
        fgn  = sigm(fmaf(p, frcpa(tf), bfv));    /* F prescaled by 4095 */         \
        xinx = fmaf(xn2, Wi[2], fmaf(xn1, Wi[1], fmaf(xn0, Wi[0], biv)));          \
        xcnx = fmaf(xn2, Wc[2], fmaf(xn1, Wc[1], fmaf(xn0, Wc[0], bcv)));          \
        xonx = fmaf(xn2, Wo[2], fmaf(xn1, Wo[1], fmaf(xn0, Wo[0], bov)));          \
    } while (0)

// ---- full step: shfl h broadcast, C (fills shfl latency), gates for step T_ ----
#define STEP(T_, SLOT_)                                                            \
    do {                                                                           \
        float h0 = __shfl_sync(0xffffffffu, h, 0);                                 \
        float h1 = __shfl_sync(0xffffffffu, h, 1);                                 \
        float h2 = __shfl_sync(0xffffffffu, h, 2);                                 \
        float h3 = __shfl_sync(0xffffffffu, h, 3);                                 \
        float h4 = __shfl_sync(0xffffffffu, h, 4);                                 \
        float h5 = __shfl_sync(0xffffffffu, h, 5);                                 \
        float h6 = __shfl_sync(0xffffffffu, h, 6);                                 \
        float h7 = __shfl_sync(0xffffffffu, h, 7);                                 \
        STEP_C(T_, SLOT_);                                                         \
        float giA = fmaf(h3, Ri[3], fmaf(h2, Ri[2], fmaf(h1, Ri[1], fmaf(h0, Ri[0], xgi)))); \
        float giB = fmaf(h7, Ri[7], fmaf(h6, Ri[6], fmaf(h5, Ri[5], h4 * Ri[4]))); \
        float gcA = fmaf(h3, Rc[3], fmaf(h2, Rc[2], fmaf(h1, Rc[1], fmaf(h0, Rc[0], xgc)))); \
        float gcB = fmaf(h7, Rc[7], fmaf(h6, Rc[6], fmaf(h5, Rc[5], h4 * Rc[4]))); \
        float goA = fmaf(h3, Ro[3], fmaf(h2, Ro[2], fmaf(h1, Ro[1], fmaf(h0, Ro[0], xgo)))); \
        float goB = fmaf(h7, Ro[7], fmaf(h6, Ro[6], fmaf(h5, Ro[5], h4 * Ro[4]))); \
        float iv = sigm(giA + giB);                                                \
        float cv = tanha(gcA + gcB);                                               \
        float ov = sigm(goA + goB);                                                \
        c = fmaf(fgv, c, iv * cv);                                                 \
        h = ov * tanha(c);                                                         \
        if (g == 0) outp[(long)(T_) * NU] = h;                                     \
        fgv = fgn; xgi = xinx; xgc = xcnx; xgo = xonx;                             \
    } while (0)

__global__ void __launch_bounds__(32, 1) siglstm_kernel(
    const float* __restrict__ inp,   // (B, T, 3)
    const float* __restrict__ ik,    // (3, 24)
    const float* __restrict__ rk,    // (8, 24)
    const float* __restrict__ fk,    // (21, 8)
    const float* __restrict__ bias,  // (32)
    float* __restrict__ out)         // (B, T, 8)
{
    const int b    = blockIdx.x;
    const int lane = threadIdx.x;
    const int u    = lane & 7;       // LSTM unit (replicated across groups)
    const int g    = lane >> 3;      // signature row / replication group

    // Per-unit weight columns (every lane loads its unit's column; groups redundant)
    float Ri[8], Rc[8], Ro[8];
#pragma unroll
    for (int k = 0; k < 8; k++) {
        Ri[k] = rk[k * 24 + u];
        Rc[k] = rk[k * 24 + 8 + u];
        Ro[k] = rk[k * 24 + 16 + u];
    }
    float Wi[3], Wc[3], Wo[3];
#pragma unroll
    for (int d = 0; d < 3; d++) {
        Wi[d] = ik[d * 24 + u];
        Wc[d] = ik[d * 24 + 8 + u];
        Wo[d] = ik[d * 24 + 16 + u];
    }
    const float biv = bias[u], bfv = bias[8 + u], bcv = bias[16 + u], bov = bias[24 + u];

    // Forget-gate coefficients for this lane's signature row, prescaled by 4095
    // (sig normalization is sig/(t/4095); we fold 4095 here, multiply by 1/t per step)
    const float SC = 4095.0f;
    const float fbase = (g == 0) ? SC * fk[0 * 8 + u] : 0.0f;   // constant sig term
    const float fL1 = SC * fk[(1 + g) * 8 + u];
    const float fR0 = SC * fk[(5 + 4 * g + 0) * 8 + u];
    const float fR1 = SC * fk[(5 + 4 * g + 1) * 8 + u];
    const float fR2 = SC * fk[(5 + 4 * g + 2) * 8 + u];
    const float fR3 = SC * fk[(5 + 4 * g + 3) * 8 + u];

    const float* __restrict__ xin = inp + (long)b * NT * ND;
    float* __restrict__ outp = out + (long)b * NT * NU + u;

    // Distributed signature state: this lane holds L1[g] and L2 row g
    float L1g = 0.0f, L2r0 = 0.0f, L2r1 = 0.0f, L2r2 = 0.0f, L2r3 = 0.0f;
    const float DX0 = 1.0f / 4095.0f;    // time increment of the augmented path

    float h, c;
    float px0, px1, px2;
    float tf = 0.0f;
    float fgv, xgi, xgc, xgo;            // pipelined: values for the step being executed
    float fgn, xinx, xcnx, xonx;         // produced by STEP_C for the next step

    // ---- t = 0: h0 = c0 = 0, so gates come from x-proj only; forget gate irrelevant ----
    {
        px0 = xin[0]; px1 = xin[1]; px2 = xin[2];
        float gi = fmaf(px2, Wi[2], fmaf(px1, Wi[1], fmaf(px0, Wi[0], biv)));
        float gc = fmaf(px2, Wc[2], fmaf(px1, Wc[1], fmaf(px0, Wc[0], bcv)));
        float go = fmaf(px2, Wo[2], fmaf(px1, Wo[1], fmaf(px0, Wo[0], bov)));
        c = sigm(gi) * tanha(gc);
        h = sigm(go) * tanha(c);
        if (g == 0) outp[0] = h;
    }

    // ---- prefetch ring: slot(t) = t & 7, fill x_1 .. x_8 ----
    float xb0[8], xb1[8], xb2[8];
#pragma unroll
    for (int t0 = 1; t0 <= 8; t0++) {
        const int s = t0 & 7;
        xb0[s] = xin[t0 * 3 + 0];
        xb1[s] = xin[t0 * 3 + 1];
        xb2[s] = xin[t0 * 3 + 2];
    }

    // ---- prologue C: compute sig/fg/xproj for step 1 (consumes slot 1, refills with x_9) ----
    STEP_C(0, 1);
    fgv = fgn; xgi = xinx; xgc = xcnx; xgo = xonx;

    // ---- main loop: t = 1 .. 4088 ----
    for (int blk = 0; blk < 511; blk++) {
#pragma unroll
        for (int j = 0; j < 8; j++) {
            const int t = 1 + blk * 8 + j;
            STEP(t, (2 + j) & 7);
        }
    }

    // ---- tail: t = 4089 .. 4095 (STEP_C beyond 4095 is clamped & unused) ----
#pragma unroll
    for (int j = 0; j < 7; j++) {
        const int t = 4089 + j;
        STEP(t, (2 + j) & 7);
    }
}

extern "C" void kernel_launch(void* const* d_in, const int* in_sizes, int n_in,
                              void* d_out, int out_size)
{
    const float* inp  = (const float*)d_in[0];   // inputs (256,4096,3)
    const float* ik   = (const float*)d_in[1];   // input_kernel (3,24)
    const float* rk   = (const float*)d_in[2];   // recurrent_kernel (8,24)
    const float* fk   = (const float*)d_in[3];   // forget_kernel (21,8)
    const float* bias = (const float*)d_in[4];   // bias (32)
    float* out = (float*)d_out;                  // (256,4096,8) f32

    siglstm_kernel<<<NB, 32>>>(inp, ik, rk, fk, bias, out);
}